// round 15
// baseline (speedup 1.0000x reference)
#include <cuda_runtime.h>
#include <cuda_fp16.h>
#include <cstdint>
#include <cstddef>

// Problem constants
#define D_DIM 256
#define NTOT  8192
#define BTOT  1024
#define KF    8
#define NBX   512                 // n-tiles per band
#define NBANDS 8                  // b-bands (by)

// GEMM: C(1024 x 73728) = xhi(1024 x 256) @ Whi^T, W rows j-major per tile:
// tile row r = j*16 + u_local.  CTA 128x144, 256 threads (4 warps M x 2 warps N),
// warp tile 32x72 -> acc 72 regs, 16 warps/SM for latency hiding.
#define BM 128
#define BN 144
#define UNITS 16
#define KC 64
#define NCHUNK 4
#define NTHREADS 256

// SMEM: resident A (all K) + 2-stage B ring + params
#define A_RES 0                          // 4 blocks of 16384 (one per 64-half chunk)
#define B_O   65536
#define BSTG  18432                      // 144 rows * 128B
#define PAR_OFF (B_O + 2*BSTG)           // 102400
#define X2_O  PAR_OFF                    // 512B, band-constant
#define ABLC_O (PAR_OFF + 512)           // 2 buffers * 1280B (ab 1152 + lc 128)
#define SMEM_TOTAL (ABLC_O + 2*1280)     // 105472

#define SWC(col, xr) ((uint32_t)(col) ^ (uint32_t)(xr))

// Scratch (static __device__, no allocation)
__device__ __align__(16) __half g_xhi[BTOT*D_DIM];
__device__ __align__(16) __half g_whi[(size_t)NTOT*9*D_DIM];   // 37.75 MB, j-major per tile
__device__ __align__(16) float2 g_ab[(size_t)NTOT*9];          // per (tile,u,j): {alpha, beta}
__device__ __align__(16) float2 g_lc[NTOT];                    // {lambda, C}
__device__ __align__(16) float  g_x2[BTOT];

// ---------------------------------------------------------------------------
__device__ __forceinline__ uint32_t smem_u32(const void* p) {
    uint32_t a;
    asm("{ .reg .u64 t; cvta.to.shared.u64 t, %1; cvt.u32.u64 %0, t; }"
        : "=r"(a) : "l"(p));
    return a;
}
__device__ __forceinline__ void cp16(uint32_t dst, const void* src) {
    asm volatile("cp.async.cg.shared.global [%0], [%1], 16;" :: "r"(dst), "l"(src));
}
__device__ __forceinline__ void cp_commit() {
    asm volatile("cp.async.commit_group;" ::: "memory");
}
__device__ __forceinline__ void cp_wait0() {
    asm volatile("cp.async.wait_group 0;" ::: "memory");
}
__device__ __forceinline__ void ldsm4(uint32_t* d, uint32_t a) {
    asm volatile("ldmatrix.sync.aligned.m8n8.x4.shared.b16 {%0,%1,%2,%3}, [%4];"
        : "=r"(d[0]), "=r"(d[1]), "=r"(d[2]), "=r"(d[3]) : "r"(a));
}
__device__ __forceinline__ void ldsm2(uint32_t* d, uint32_t a) {
    asm volatile("ldmatrix.sync.aligned.m8n8.x2.shared.b16 {%0,%1}, [%2];"
        : "=r"(d[0]), "=r"(d[1]) : "r"(a));
}
__device__ __forceinline__ void mma16816(float* c, const uint32_t* a, const uint32_t* b) {
    asm volatile(
        "mma.sync.aligned.m16n8k16.row.col.f32.f16.f16.f32 "
        "{%0,%1,%2,%3}, {%4,%5,%6,%7}, {%8,%9}, {%0,%1,%2,%3};"
        : "+f"(c[0]), "+f"(c[1]), "+f"(c[2]), "+f"(c[3])
        : "r"(a[0]), "r"(a[1]), "r"(a[2]), "r"(a[3]), "r"(b[0]), "r"(b[1]));
}

// ---------------------------------------------------------------------------
// Fused precompute: blocks [0,1024) -> x path; [1024,9216) -> W path
__global__ void precomp_kernel(const float* __restrict__ x,
                               const float* __restrict__ mu,
                               const float* __restrict__ v,
                               const float* __restrict__ lambda_base,
                               const float* __restrict__ omega) {
    __shared__ float mus[256];
    __shared__ float part[8];
    __shared__ float muvs[8];
    __shared__ float mu2s;
    const int t = threadIdx.x, w = t >> 5, l = t & 31;

    if (blockIdx.x < BTOT) {
        int b = blockIdx.x;
        float val = x[b * D_DIM + t];
        g_xhi[b * D_DIM + t] = __float2half_rn(val);
        float s = val * val;
        #pragma unroll
        for (int o = 16; o > 0; o >>= 1) s += __shfl_down_sync(0xffffffffu, s, o);
        if (l == 0) part[w] = s;
        __syncthreads();
        if (t == 0) {
            float tot = 0.f;
            #pragma unroll
            for (int i = 0; i < 8; i++) tot += part[i];
            g_x2[b] = tot;
        }
        return;
    }

    const int n = blockIdx.x - BTOT;
    const int bxw = n >> 4, ul = n & 15;
    float m = mu[(size_t)n * D_DIM + t];
    mus[t] = m;
    g_whi[((size_t)bxw * 144 + ul) * D_DIM + t] = __float2half_rn(m);
    float s = m * m;
    #pragma unroll
    for (int o = 16; o > 0; o >>= 1) s += __shfl_down_sync(0xffffffffu, s, o);
    if (l == 0) part[w] = s;
    __syncthreads();
    if (t == 0) {
        float tot = 0.f;
        #pragma unroll
        for (int i = 0; i < 8; i++) tot += part[i];
        mu2s = tot;
    }
    const float* vk = v + ((size_t)n * KF + w) * D_DIM + l * 8;
    float4 p0 = *(const float4*)(vk);
    float4 p1 = *(const float4*)(vk + 4);
    float fv[8] = {p0.x, p0.y, p0.z, p0.w, p1.x, p1.y, p1.z, p1.w};
    __half hh[8];
    float hv[8];
    #pragma unroll
    for (int i = 0; i < 8; i++) {
        hh[i] = __float2half_rn(fv[i]);
        hv[i] = __half2float(hh[i]);
    }
    uint4 pk;
    pk.x = (uint32_t)__half_as_ushort(hh[0]) | ((uint32_t)__half_as_ushort(hh[1]) << 16);
    pk.y = (uint32_t)__half_as_ushort(hh[2]) | ((uint32_t)__half_as_ushort(hh[3]) << 16);
    pk.z = (uint32_t)__half_as_ushort(hh[4]) | ((uint32_t)__half_as_ushort(hh[5]) << 16);
    pk.w = (uint32_t)__half_as_ushort(hh[6]) | ((uint32_t)__half_as_ushort(hh[7]) << 16);
    *(uint4*)(g_whi + ((size_t)bxw * 144 + (w + 1) * 16 + ul) * D_DIM + l * 8) = pk;
    float dot = 0.f;
    #pragma unroll
    for (int i = 0; i < 8; i++) dot = fmaf(mus[l * 8 + i], hv[i], dot);
    #pragma unroll
    for (int o = 16; o > 0; o >>= 1) dot += __shfl_down_sync(0xffffffffu, dot, o);
    if (l == 0) muvs[w] = dot;
    __syncthreads();

    if (t < 9) {
        float lam = lambda_base[n];
        float2 ab;
        if (t == 0) {
            ab.x = 0.f;
            ab.y = -2.f * lam;
        } else {
            float om = omega[n * KF + t - 1];
            ab.x = om;
            ab.y = -2.f * om * muvs[t - 1];
        }
        g_ab[(size_t)bxw * 144 + ul * 9 + t] = ab;
    }
    if (t == 0) {
        float lam = lambda_base[n];
        float C = lam * mu2s;
        #pragma unroll
        for (int k = 0; k < KF; k++) {
            float om = omega[n * KF + k];
            C = fmaf(om * muvs[k], muvs[k], C);
        }
        float2 lc;
        lc.x = lam;
        lc.y = C;
        g_lc[n] = lc;
    }
}

// ---------------------------------------------------------------------------
__global__ void __launch_bounds__(NTHREADS, 2)
hmu_mma_kernel(float* __restrict__ out) {
    extern __shared__ __align__(1024) char smem[];
    const uint32_t sb = smem_u32(smem);

    const int t    = threadIdx.x;
    const int wid  = t >> 5;
    const int lane = t & 31;
    const int wm   = wid & 3;       // 4 warps in M (32 rows each)
    const int wn   = wid >> 2;      // 2 warps in N (8 units each)
    const int tg   = lane >> 2, tk = lane & 3;

    const int per_band = gridDim.x >> 3;            // CTAs per by-band
    const int band = blockIdx.x / per_band;         // = by
    const int idx0 = blockIdx.x - band * per_band;
    const int by   = band;

    // ldmatrix lane addressing
    const int mq = lane >> 3, rr = lane & 7;
    const uint32_t xorR  = (uint32_t)rr * 16;
    const uint32_t rowA  = (uint32_t)(wm * 32 + (mq & 1) * 8 + rr);
    const uint32_t colA  = (uint32_t)((mq >> 1) * 16);
    const uint32_t rowBb = (uint32_t)(16 * (mq >> 1) + 8 * wn + rr);  // + 32*n2
    const uint32_t colB  = (uint32_t)((mq & 1) * 16);
    const uint32_t rowB2 = (uint32_t)(128 + 8 * wn + rr);
    const uint32_t colB2 = (uint32_t)(((lane >> 3) & 1) * 16);

    // B chunk loader; pp>=0 also prefetches next tile's (ab,lc) into buffer pp
    auto load_B = [&](int bx, int s, int buf, int pp) {
        const int d0 = s * KC;
        const uint32_t stB = sb + B_O + (uint32_t)buf * BSTG;
        #pragma unroll
        for (int i = 0; i < 4; i++) {
            int idx = t + NTHREADS * i;
            int r = idx >> 3, c = idx & 7;
            cp16(stB + r * 128 + SWC(c * 16, (r & 7) * 16),
                 g_whi + ((size_t)bx * BN + r) * D_DIM + d0 + c * 8);
        }
        if (t < 128) {
            int idx = 1024 + t;
            int r = idx >> 3, c = idx & 7;
            cp16(stB + r * 128 + SWC(c * 16, (r & 7) * 16),
                 g_whi + ((size_t)bx * BN + r) * D_DIM + d0 + c * 8);
        }
        if (pp >= 0) {
            uint32_t pb = sb + ABLC_O + (uint32_t)pp * 1280;
            int tt = t - 128;
            if (tt >= 0 && tt < 72)
                cp16(pb + tt * 16, (const char*)(g_ab + (size_t)bx * 144) + tt * 16);
            else if (tt >= 72 && tt < 80)
                cp16(pb + 1152 + (tt - 72) * 16, (const char*)(g_lc + bx * 16) + (tt - 72) * 16);
        }
    };

    // ---- prologue: resident A (all 4 chunks), band x2, first B chunk + params ----
    #pragma unroll
    for (int c = 0; c < 4; c++) {
        #pragma unroll
        for (int i = 0; i < 4; i++) {
            int idx = t + NTHREADS * i;
            int r = idx >> 3, cc = idx & 7;
            cp16(sb + A_RES + c * 16384 + r * 128 + SWC(cc * 16, (r & 7) * 16),
                 g_xhi + (size_t)(by * BM + r) * D_DIM + c * KC + cc * 8);
        }
    }
    if (t < 32) cp16(sb + X2_O + t * 16, (const char*)(g_x2 + by * BM) + t * 16);
    load_B(idx0, 0, 0, 0);
    cp_commit();

    float acc[2][9][4];
    int tp = 0;

    for (int bx = idx0; bx < NBX; bx += per_band, tp ^= 1) {
        #pragma unroll
        for (int mi = 0; mi < 2; mi++)
            #pragma unroll
            for (int ni = 0; ni < 9; ni++)
                #pragma unroll
                for (int r = 0; r < 4; r++) acc[mi][ni][r] = 0.f;

        for (int s = 0; s < NCHUNK; s++) {
            cp_wait0();
            __syncthreads();
            {   // issue next B chunk (may roll into next tile, carrying params)
                int s2 = s + 1, bx2 = bx, pp = -1;
                if (s2 == NCHUNK) { s2 = 0; bx2 = bx + per_band; pp = tp ^ 1; }
                if (bx2 < NBX) load_B(bx2, s2, (s + 1) & 1, pp);
                cp_commit();
            }
            const uint32_t stA = sb + A_RES + (uint32_t)s * 16384;
            const uint32_t stB = sb + B_O + (uint32_t)(s & 1) * BSTG;
            #pragma unroll
            for (int ks = 0; ks < 4; ks++) {
                const uint32_t kb = ks * 32;
                uint32_t ah[2][4];
                #pragma unroll
                for (int mi = 0; mi < 2; mi++)
                    ldsm4(ah[mi], stA + (rowA + mi * 16) * 128 + SWC(colA + kb, xorR));
                #pragma unroll
                for (int n2 = 0; n2 < 4; n2++) {
                    uint32_t bf[4];
                    ldsm4(bf, stB + (rowBb + 32 * n2) * 128 + SWC(colB + kb, xorR));
                    #pragma unroll
                    for (int mi = 0; mi < 2; mi++) {
                        mma16816(acc[mi][2 * n2],     ah[mi], bf);
                        mma16816(acc[mi][2 * n2 + 1], ah[mi], bf + 2);
                    }
                }
                {
                    uint32_t bf2[2];
                    ldsm2(bf2, stB + rowB2 * 128 + SWC(colB2 + kb, xorR));
                    #pragma unroll
                    for (int mi = 0; mi < 2; mi++)
                        mma16816(acc[mi][8], ah[mi], bf2);
                }
            }
        }

        // ---- register epilogue: lane owns units ua, ua+1 across all 9 j ----
        {
            const char* pb = smem + ABLC_O + tp * 1280;
            const float2* abp = (const float2*)pb;
            const float2* lcp = (const float2*)(pb + 1152);
            const float*  x2p = (const float*)(smem + X2_O);
            const int ua = 8 * wn + 2 * tk;
            float2 A0[9], A1[9];
            #pragma unroll
            for (int j = 0; j < 9; j++) {
                A0[j] = abp[ua * 9 + j];
                A1[j] = abp[ua * 9 + 9 + j];
            }
            const float2 lca = lcp[ua], lcb = lcp[ua + 1];
            float* ob = out + (size_t)(by * BM) * NTOT + bx * UNITS + ua;
            #pragma unroll
            for (int mi = 0; mi < 2; mi++)
                #pragma unroll
                for (int rh = 0; rh < 2; rh++) {
                    const int row = wm * 32 + mi * 16 + tg + rh * 8;
                    const float x2r = x2p[row];
                    float qa = fmaf(lca.x, x2r, lca.y);
                    float qb = fmaf(lcb.x, x2r, lcb.y);
                    #pragma unroll
                    for (int j = 0; j < 9; j++) {
                        float da = acc[mi][j][rh * 2 + 0];
                        float db = acc[mi][j][rh * 2 + 1];
                        qa = fmaf(da, fmaf(A0[j].x, da, A0[j].y), qa);
                        qb = fmaf(db, fmaf(A1[j].x, db, A1[j].y), qb);
                    }
                    float2 o;
                    o.x = __expf(qa * (-1.0f / 256.0f));
                    o.y = __expf(qb * (-1.0f / 256.0f));
                    *(float2*)(ob + (size_t)row * NTOT) = o;
                }
        }
    }
}

// ---------------------------------------------------------------------------
extern "C" void kernel_launch(void* const* d_in, const int* in_sizes, int n_in,
                              void* d_out, int out_size) {
    const float *x = nullptr, *mu = nullptr, *lam = nullptr, *v = nullptr, *om = nullptr;
    for (int i = 0; i < n_in; i++) {
        switch (in_sizes[i]) {
            case BTOT * D_DIM:      x   = (const float*)d_in[i]; break;
            case NTOT * D_DIM:      mu  = (const float*)d_in[i]; break;
            case NTOT:              lam = (const float*)d_in[i]; break;
            case NTOT * KF * D_DIM: v   = (const float*)d_in[i]; break;
            case NTOT * KF:         om  = (const float*)d_in[i]; break;
        }
    }

    precomp_kernel<<<BTOT + NTOT, 256>>>(x, mu, v, lam, om);

    int nsm = 0;
    cudaDeviceGetAttribute(&nsm, cudaDevAttrMultiProcessorCount, 0);
    if (nsm <= 0) nsm = 148;
    int per_band = (2 * nsm) / NBANDS;          // 38 on 152-SM GB300
    if (per_band < 1) per_band = 1;
    int grid = NBANDS * per_band;

    cudaFuncSetAttribute(hmu_mma_kernel,
                         cudaFuncAttributeMaxDynamicSharedMemorySize, SMEM_TOTAL);
    hmu_mma_kernel<<<grid, NTHREADS, SMEM_TOTAL>>>((float*)d_out);
}